// round 1
// baseline (speedup 1.0000x reference)
#include <cuda_runtime.h>
#include <math.h>
#include <stdint.h>

// Problem constants
#define DD    512
#define KC    1024
#define QL    8
#define NTOK  16384
#define MT    64          // tokens per CTA
#define CCH   128         // codes per chunk
#define DS    32          // d-slice per smem stage
#define RSTR  68          // residual smem row stride (pad vs 64)
#define CSTR  132         // code-tile smem row stride (pad vs 128)
#define NCTA  (NTOK / MT) // 256

#define IDXOFF ((size_t)NTOK * DD)           // 8388608
#define SCLOFF (IDXOFF + (size_t)NTOK * QL)  // 8519680

// Scratch (static device allocations are allowed; no cudaMalloc anywhere)
__device__ float  g_csq[QL * KC];
__device__ int    g_cnt[QL * KC];
__device__ double g_commit[QL];
__device__ float  g_qsum[(size_t)NTOK * DD];

// ---------------------------------------------------------------------------
// Prep: per-code squared norms (sequential order, matches jnp.sum), zero stats
// ---------------------------------------------------------------------------
__global__ void rvq_prep(const float* __restrict__ cb) {
    int i = blockIdx.x * blockDim.x + threadIdx.x;
    if (i < QL * KC) {
        const float* c = cb + (size_t)i * DD;
        float s = 0.f;
        for (int d = 0; d < DD; ++d) { float v = c[d]; s += v * v; }
        g_csq[i] = s;
        g_cnt[i] = 0;
    }
    if (i < QL) g_commit[i] = 0.0;
}

// ---------------------------------------------------------------------------
// Main fused kernel: residual tile resident in smem across all 8 levels.
// Per level: tiled fp32 GEMM (dist) + argmin (lowest-index ties) + gather +
// residual/qsum update + per-token rsq for next level (== commit terms).
// ---------------------------------------------------------------------------
__global__ void __launch_bounds__(256, 1)
rvq_main(const float* __restrict__ x, const float* __restrict__ cb,
         float* __restrict__ out) {
    extern __shared__ char smraw[];
    float* res  = (float*)smraw;                    // [512][68]
    float* cbs  = res + DD * RSTR;                  // [32][132]
    float* redv = cbs + DS * CSTR;                  // [16][64]
    int*   redi = (int*)(redv + 16 * 64);           // [16][64]
    float* rsqp = (float*)(redi + 16 * 64);         // [4][64]
    float* rsq  = rsqp + 4 * 64;                    // [64]
    int*   idxs = (int*)(rsq + 64);                 // [64]

    const int tid  = threadIdx.x;
    const int tok0 = blockIdx.x * MT;

    // GEMM thread mapping: 16 token-groups x 16 code-groups
    const int tg = tid & 15;   // tokens tg*4 .. tg*4+3
    const int cg = tid >> 4;   // codes  cg*8 .. cg*8+7 within chunk

    // update-phase mapping: 4 threads per token
    const int tsub  = tid & 3;
    const int tloc  = tid >> 2;         // 0..63
    const int dbase = tsub * 128;

    // ---- initial load: x -> res (transposed) + rsq partials (fixed order)
    {
        const float* xp = x + (size_t)(tok0 + tloc) * DD + dbase;
        float s = 0.f;
        #pragma unroll 4
        for (int j = 0; j < 128; j += 4) {
            float4 v = *(const float4*)(xp + j);
            int da = (dbase + j) * RSTR + tloc;
            res[da] = v.x; res[da + RSTR] = v.y;
            res[da + 2 * RSTR] = v.z; res[da + 3 * RSTR] = v.w;
            s += v.x * v.x; s += v.y * v.y; s += v.z * v.z; s += v.w * v.w;
        }
        rsqp[tsub * 64 + tloc] = s;
    }
    __syncthreads();
    if (tid < MT)
        rsq[tid] = ((rsqp[tid] + rsqp[64 + tid]) + rsqp[128 + tid]) + rsqp[192 + tid];
    // (slice-loop syncthreads below orders this write before first read)

    for (int l = 0; l < QL; ++l) {
        const float* cbl  = cb + (size_t)l * KC * DD;
        const float* csql = g_csq + l * KC;

        float bestv[4]; int besti[4];
        #pragma unroll
        for (int i = 0; i < 4; ++i) { bestv[i] = __int_as_float(0x7f800000); besti[i] = 0; }

        float acc[4][8];
        // prefetch registers for the code slice (4 float4 per thread)
        float4 pf[4];
        {
            // slice 0 of chunk 0
            #pragma unroll
            for (int i = 0; i < 4; ++i) {
                int f4 = i * 256 + tid;
                int code = f4 >> 3, seg = f4 & 7;
                pf[i] = *(const float4*)(cbl + (size_t)code * DD + (seg << 2));
            }
        }

        #pragma unroll 1
        for (int step = 0; step < (KC / CCH) * (DD / DS); ++step) {
            const int kc = (step >> 4) * CCH;   // 16 slices per chunk
            const int sl = step & 15;

            if (sl == 0) {
                #pragma unroll
                for (int i = 0; i < 4; ++i)
                    #pragma unroll
                    for (int j = 0; j < 8; ++j) acc[i][j] = 0.f;
            }

            __syncthreads();   // previous compute done before overwriting cbs
            #pragma unroll
            for (int i = 0; i < 4; ++i) {
                int f4 = i * 256 + tid;
                int code = f4 >> 3, seg = f4 & 7;
                float* dst = &cbs[(seg * 4) * CSTR + code];
                dst[0] = pf[i].x; dst[CSTR] = pf[i].y;
                dst[2 * CSTR] = pf[i].z; dst[3 * CSTR] = pf[i].w;
            }
            __syncthreads();

            // prefetch next slice (global latency overlapped with FMA loop)
            if (step + 1 < (KC / CCH) * (DD / DS)) {
                const int nkc = ((step + 1) >> 4) * CCH;
                const int nd0 = ((step + 1) & 15) * DS;
                #pragma unroll
                for (int i = 0; i < 4; ++i) {
                    int f4 = i * 256 + tid;
                    int code = f4 >> 3, seg = f4 & 7;
                    pf[i] = *(const float4*)(cbl + (size_t)(nkc + code) * DD + nd0 + (seg << 2));
                }
            }

            const int d0 = sl * DS;
            #pragma unroll 8
            for (int dd = 0; dd < DS; ++dd) {
                float4 a  = *(const float4*)&res[(d0 + dd) * RSTR + (tg << 2)];
                const float* bp = &cbs[dd * CSTR + (cg << 3)];
                float4 b0 = *(const float4*)bp;
                float4 b1 = *(const float4*)(bp + 4);
                float ar[4] = {a.x, a.y, a.z, a.w};
                float br[8] = {b0.x, b0.y, b0.z, b0.w, b1.x, b1.y, b1.z, b1.w};
                #pragma unroll
                for (int i = 0; i < 4; ++i)
                    #pragma unroll
                    for (int j = 0; j < 8; ++j)
                        acc[i][j] = fmaf(ar[i], br[j], acc[i][j]);
            }

            if (sl == 15) {
                // dist = fl(fl(rsq - 2*dot) + csq); 2*dot exact -> fma matches ref
                #pragma unroll
                for (int i = 0; i < 4; ++i) {
                    float rq = rsq[(tg << 2) + i];
                    #pragma unroll
                    for (int j = 0; j < 8; ++j) {
                        int code = kc + (cg << 3) + j;
                        float dist = fmaf(-2.f, acc[i][j], rq) + csql[code];
                        if (dist < bestv[i]) { bestv[i] = dist; besti[i] = code; }
                    }
                }
            }
        }

        // ---- cross-thread argmin reduce (lexicographic: lowest index on tie)
        __syncthreads();
        #pragma unroll
        for (int i = 0; i < 4; ++i) {
            redv[cg * 64 + (tg << 2) + i] = bestv[i];
            redi[cg * 64 + (tg << 2) + i] = besti[i];
        }
        __syncthreads();
        if (tid < MT) {
            float bv = redv[tid]; int bi = redi[tid];
            #pragma unroll 1
            for (int c = 1; c < 16; ++c) {
                float v = redv[c * 64 + tid]; int ix = redi[c * 64 + tid];
                if (v < bv || (v == bv && ix < bi)) { bv = v; bi = ix; }
            }
            idxs[tid] = bi;
            out[IDXOFF + (size_t)(tok0 + tid) * QL + l] = (float)bi;
            atomicAdd(&g_cnt[l * KC + bi], 1);
        }
        __syncthreads();

        // ---- gather + residual/qsum update + rsq partials for next level
        {
            const int myidx = idxs[tloc];
            const float* qv = cbl + (size_t)myidx * DD + dbase;
            float* qs = g_qsum + (size_t)(tok0 + tloc) * DD + dbase;
            const float* xp = x + (size_t)(tok0 + tloc) * DD + dbase;
            float* op = out + (size_t)(tok0 + tloc) * DD + dbase;
            float s = 0.f;
            #pragma unroll 4
            for (int j = 0; j < 128; j += 4) {
                float4 q = *(const float4*)(qv + j);
                int da = (dbase + j) * RSTR + tloc;
                float r0 = res[da]            - q.x;
                float r1 = res[da + RSTR]     - q.y;
                float r2 = res[da + 2 * RSTR] - q.z;
                float r3 = res[da + 3 * RSTR] - q.w;
                res[da] = r0; res[da + RSTR] = r1;
                res[da + 2 * RSTR] = r2; res[da + 3 * RSTR] = r3;
                s += r0 * r0; s += r1 * r1; s += r2 * r2; s += r3 * r3;

                float4 qa;
                if (l == 0) {
                    qa = q;
                } else {
                    float4 o = *(const float4*)(qs + j);
                    qa.x = o.x + q.x; qa.y = o.y + q.y;
                    qa.z = o.z + q.z; qa.w = o.w + q.w;
                }
                *(float4*)(qs + j) = qa;

                if (l == QL - 1) {
                    float4 xv = *(const float4*)(xp + j);
                    float4 ov;
                    ov.x = xv.x + (qa.x - xv.x);
                    ov.y = xv.y + (qa.y - xv.y);
                    ov.z = xv.z + (qa.z - xv.z);
                    ov.w = xv.w + (qa.w - xv.w);
                    *(float4*)(op + j) = ov;
                }
            }
            rsqp[tsub * 64 + tloc] = s;
        }
        __syncthreads();
        if (tid < MT)
            rsq[tid] = ((rsqp[tid] + rsqp[64 + tid]) + rsqp[128 + tid]) + rsqp[192 + tid];
        __syncthreads();
        if (tid == 0) {
            double cs = 0.0;
            for (int t = 0; t < MT; ++t) cs += (double)rsq[t];
            atomicAdd(&g_commit[l], cs);   // commit_l = mean(r_new^2)
        }
        // slice-loop sync at next level orders everything
    }
}

// ---------------------------------------------------------------------------
// Finalize: commitment loss + perplexity scalars
// ---------------------------------------------------------------------------
__global__ void rvq_fin(float* __restrict__ out) {
    __shared__ double red[256];
    const int tid = threadIdx.x;
    double psum = 0.0;
    for (int l = 0; l < QL; ++l) {
        double s = 0.0;
        for (int k = tid; k < KC; k += 256) {
            double p = (double)g_cnt[l * KC + k] / (double)NTOK;
            s += p * log(p + 1e-10);
        }
        red[tid] = s;
        __syncthreads();
        for (int off = 128; off > 0; off >>= 1) {
            if (tid < off) red[tid] += red[tid + off];
            __syncthreads();
        }
        if (tid == 0) psum += exp(-red[0]);
        __syncthreads();
    }
    if (tid == 0) {
        double closs = 0.0;
        for (int l = 0; l < QL; ++l)
            closs += g_commit[l] / ((double)NTOK * (double)DD);
        out[SCLOFF]     = (float)(0.25 * closs);
        out[SCLOFF + 1] = (float)(psum / (double)QL);
    }
}

// ---------------------------------------------------------------------------
extern "C" void kernel_launch(void* const* d_in, const int* in_sizes, int n_in,
                              void* d_out, int out_size) {
    const float* x  = (const float*)d_in[0];
    const float* cb = (const float*)d_in[1];
    float* out = (float*)d_out;

    const int smem = (DD * RSTR + DS * CSTR + 16 * 64 * 2 + 4 * 64 + 64 + 64) * 4;
    cudaFuncSetAttribute(rvq_main, cudaFuncAttributeMaxDynamicSharedMemorySize, smem);

    rvq_prep<<<(QL * KC + 255) / 256, 256>>>(cb);
    rvq_main<<<NCTA, 256, smem>>>(x, cb, out);
    rvq_fin<<<1, 256>>>(out);
}